// round 4
// baseline (speedup 1.0000x reference)
#include <cuda_runtime.h>
#include <math.h>

#define B_  4
#define L_  2048
#define DM  1024
#define H_  16
#define DK  64
#define MROWS (B_ * L_)          // 8192

// ---------------- scratch (device globals; no allocation allowed) ----------
__device__ float g_h[(size_t)MROWS * DM];            // 32 MB  layernorm out
__device__ float g_qkv[(size_t)MROWS * 3 * DM];      // 96 MB  qkv (rope in place)
__device__ float g_o[(size_t)MROWS * DM];            // 32 MB  attention out
__device__ float g_cos[L_ * 32];
__device__ float g_sin[L_ * 32];

// ---------------- LayerNorm: one block per row (1024 elems, 256 thr) -------
__global__ void ln_kernel(const float* __restrict__ x, float* __restrict__ h) {
    __shared__ float red[8];
    int row = blockIdx.x;
    const float4* xr = (const float4*)(x + (size_t)row * DM);
    float4 v = xr[threadIdx.x];

    float s = v.x + v.y + v.z + v.w;
    #pragma unroll
    for (int o = 16; o; o >>= 1) s += __shfl_xor_sync(0xffffffffu, s, o);
    if ((threadIdx.x & 31) == 0) red[threadIdx.x >> 5] = s;
    __syncthreads();
    float tot = red[0] + red[1] + red[2] + red[3] + red[4] + red[5] + red[6] + red[7];
    float mean = tot * (1.0f / 1024.0f);

    float dx = v.x - mean, dy = v.y - mean, dz = v.z - mean, dw = v.w - mean;
    float sq = dx * dx + dy * dy + dz * dz + dw * dw;
    __syncthreads();
    #pragma unroll
    for (int o = 16; o; o >>= 1) sq += __shfl_xor_sync(0xffffffffu, sq, o);
    if ((threadIdx.x & 31) == 0) red[threadIdx.x >> 5] = sq;
    __syncthreads();
    float var = (red[0] + red[1] + red[2] + red[3] + red[4] + red[5] + red[6] + red[7])
                * (1.0f / 1024.0f);
    float inv = rsqrtf(var + 1e-8f);

    float4 o4 = make_float4(dx * inv, dy * inv, dz * inv, dw * inv);
    ((float4*)(h + (size_t)row * DM))[threadIdx.x] = o4;
}

// ---------------- RoPE table (double precision, tiny) ----------------------
__global__ void rope_table_kernel(float* __restrict__ ct, float* __restrict__ st) {
    int idx = blockIdx.x * blockDim.x + threadIdx.x;   // 65536 total
    int l = idx >> 5;
    int i = idx & 31;
    double inv = exp(-(double)i * (log(10000.0) / 32.0));
    double a = (double)l * inv;
    ct[idx] = (float)cos(a);
    st[idx] = (float)sin(a);
}

// ---------------- RoPE apply, in place on q and k sections of qkv ----------
__global__ void rope_apply_kernel(float* __restrict__ qkv,
                                  const float* __restrict__ ct,
                                  const float* __restrict__ st) {
    int idx = blockIdx.x * blockDim.x + threadIdx.x;   // 8,388,608 total
    int pair = idx & 31;
    int head = (idx >> 5) & 15;
    int sec  = (idx >> 9) & 1;          // 0 = q, 1 = k
    int row  = idx >> 10;               // 0..8191
    int l    = row & (L_ - 1);
    size_t off = (size_t)row * 3072 + sec * 1024 + head * 64 + pair * 2;
    float2 v = *(float2*)(qkv + off);
    int ti = l * 32 + pair;
    float c = ct[ti], s = st[ti];
    float2 r = make_float2(v.x * c - v.y * s, v.x * s + v.y * c);
    *(float2*)(qkv + off) = r;
}

// ---------------- NT SGEMM: C[M,N] = A[M,K] * B[N,K]^T, fp32 ---------------
// 128x128x16 tiles, 256 threads, 8x8 microtiles.
__global__ __launch_bounds__(256, 2)
void sgemm_nt(const float* __restrict__ A, const float* __restrict__ Bm,
              float* __restrict__ C, int M, int N, int K) {
    __shared__ float As[16][128];
    __shared__ float Bs[16][128];
    int bx = blockIdx.x, by = blockIdx.y;
    int tid = threadIdx.x;
    int tx = tid & 15, ty = tid >> 4;

    float acc[8][8];
    #pragma unroll
    for (int i = 0; i < 8; ++i)
        #pragma unroll
        for (int j = 0; j < 8; ++j) acc[i][j] = 0.f;

    const float* Ab = A + (size_t)by * 128 * K;
    const float* Bb = Bm + (size_t)bx * 128 * K;
    int lr = tid >> 1;               // row within tile (0..127)
    int lc = (tid & 1) * 8;          // k-col base (0 or 8)

    for (int k0 = 0; k0 < K; k0 += 16) {
        float4 a0 = *(const float4*)(Ab + (size_t)lr * K + k0 + lc);
        float4 a1 = *(const float4*)(Ab + (size_t)lr * K + k0 + lc + 4);
        float4 b0 = *(const float4*)(Bb + (size_t)lr * K + k0 + lc);
        float4 b1 = *(const float4*)(Bb + (size_t)lr * K + k0 + lc + 4);
        As[lc + 0][lr] = a0.x; As[lc + 1][lr] = a0.y;
        As[lc + 2][lr] = a0.z; As[lc + 3][lr] = a0.w;
        As[lc + 4][lr] = a1.x; As[lc + 5][lr] = a1.y;
        As[lc + 6][lr] = a1.z; As[lc + 7][lr] = a1.w;
        Bs[lc + 0][lr] = b0.x; Bs[lc + 1][lr] = b0.y;
        Bs[lc + 2][lr] = b0.z; Bs[lc + 3][lr] = b0.w;
        Bs[lc + 4][lr] = b1.x; Bs[lc + 5][lr] = b1.y;
        Bs[lc + 6][lr] = b1.z; Bs[lc + 7][lr] = b1.w;
        __syncthreads();
        #pragma unroll
        for (int k = 0; k < 16; ++k) {
            float a[8], b[8];
            *(float4*)&a[0] = *(const float4*)&As[k][ty * 8];
            *(float4*)&a[4] = *(const float4*)&As[k][ty * 8 + 4];
            *(float4*)&b[0] = *(const float4*)&Bs[k][tx * 8];
            *(float4*)&b[4] = *(const float4*)&Bs[k][tx * 8 + 4];
            #pragma unroll
            for (int i = 0; i < 8; ++i)
                #pragma unroll
                for (int j = 0; j < 8; ++j)
                    acc[i][j] += a[i] * b[j];
        }
        __syncthreads();
    }

    float* Cb = C + (size_t)(by * 128 + ty * 8) * N + bx * 128 + tx * 8;
    #pragma unroll
    for (int i = 0; i < 8; ++i) {
        *(float4*)(Cb + (size_t)i * N)     = make_float4(acc[i][0], acc[i][1], acc[i][2], acc[i][3]);
        *(float4*)(Cb + (size_t)i * N + 4) = make_float4(acc[i][4], acc[i][5], acc[i][6], acc[i][7]);
    }
}

// ---------------- Flash attention (causal), fp32 ---------------------------
// grid (L/64, H, B), 256 threads. BQ=BK=64, D=64. 4x4 microtiles.
// Smem: Qs 64x64, Ks 64x68 (reused for P), Vs 64x68 -> 51200 B dynamic.
#define ATTN_SMEM ((64 * 64 + 2 * 64 * 68) * 4)
#define NEG_BIG (-1e30f)

__global__ __launch_bounds__(256)
void attn_kernel(const float* __restrict__ qkv, float* __restrict__ out) {
    extern __shared__ float sm[];
    float* Qs = sm;                 // 64 x 64
    float* Ks = Qs + 64 * 64;       // 64 x 68, reused as P after softmax
    float* Vs = Ks + 64 * 68;       // 64 x 68

    int qi = blockIdx.x, h = blockIdx.y, b = blockIdx.z;
    int tid = threadIdx.x;
    int tx = tid & 15, ty = tid >> 4;
    const float scale = 0.125f;     // 1/sqrt(64)

    // Load + pre-scale Q tile
    for (int i = tid; i < 64 * 16; i += 256) {
        int r = i >> 4, c = (i & 15) << 2;
        const float* p = qkv + (size_t)(b * L_ + qi * 64 + r) * 3072 + h * 64 + c;
        float4 v = *(const float4*)p;
        v.x *= scale; v.y *= scale; v.z *= scale; v.w *= scale;
        *(float4*)(Qs + r * 64 + c) = v;
    }

    float acc[4][4];
    #pragma unroll
    for (int r = 0; r < 4; ++r)
        #pragma unroll
        for (int c = 0; c < 4; ++c) acc[r][c] = 0.f;
    float mreg[4], lreg[4];
    #pragma unroll
    for (int r = 0; r < 4; ++r) { mreg[r] = NEG_BIG; lreg[r] = 0.f; }

    for (int kt = 0; kt <= qi; ++kt) {
        __syncthreads();   // protect Ks/Vs (PV of prev iter done); orders Q stores too
        for (int i = tid; i < 64 * 16; i += 256) {
            int r = i >> 4, c = (i & 15) << 2;
            const float* p = qkv + (size_t)(b * L_ + kt * 64 + r) * 3072 + 1024 + h * 64 + c;
            *(float4*)(Ks + r * 68 + c) = *(const float4*)p;
            *(float4*)(Vs + r * 68 + c) = *(const float4*)(p + 1024);
        }
        __syncthreads();

        // S = Q K^T  (4x4 per thread)
        float s4[4][4];
        #pragma unroll
        for (int r = 0; r < 4; ++r)
            #pragma unroll
            for (int c = 0; c < 4; ++c) s4[r][c] = 0.f;
        #pragma unroll 4
        for (int d4 = 0; d4 < 16; ++d4) {
            float4 a[4], bb[4];
            #pragma unroll
            for (int r = 0; r < 4; ++r)
                a[r] = *(const float4*)(Qs + (ty * 4 + r) * 64 + d4 * 4);
            #pragma unroll
            for (int c = 0; c < 4; ++c)
                bb[c] = *(const float4*)(Ks + (tx * 4 + c) * 68 + d4 * 4);
            #pragma unroll
            for (int r = 0; r < 4; ++r)
                #pragma unroll
                for (int c = 0; c < 4; ++c)
                    s4[r][c] += a[r].x * bb[c].x + a[r].y * bb[c].y
                              + a[r].z * bb[c].z + a[r].w * bb[c].w;
        }
        if (kt == qi) {   // causal mask inside diagonal tile
            #pragma unroll
            for (int r = 0; r < 4; ++r)
                #pragma unroll
                for (int c = 0; c < 4; ++c)
                    if (tx * 4 + c > ty * 4 + r) s4[r][c] = NEG_BIG;
        }

        // Online softmax in registers; row groups are 16 xor-shuffle lanes
        float alpha[4];
        #pragma unroll
        for (int r = 0; r < 4; ++r) {
            float mx = fmaxf(fmaxf(s4[r][0], s4[r][1]), fmaxf(s4[r][2], s4[r][3]));
            #pragma unroll
            for (int o = 8; o; o >>= 1) mx = fmaxf(mx, __shfl_xor_sync(0xffffffffu, mx, o));
            mx = fmaxf(mx, mreg[r]);
            float sum = 0.f;
            #pragma unroll
            for (int c = 0; c < 4; ++c) {
                float p = __expf(s4[r][c] - mx);
                s4[r][c] = p;
                sum += p;
            }
            #pragma unroll
            for (int o = 8; o; o >>= 1) sum += __shfl_xor_sync(0xffffffffu, sum, o);
            alpha[r] = __expf(mreg[r] - mx);
            lreg[r] = lreg[r] * alpha[r] + sum;
            mreg[r] = mx;
        }

        __syncthreads();   // everyone done reading Ks
        #pragma unroll
        for (int r = 0; r < 4; ++r)
            #pragma unroll
            for (int c = 0; c < 4; ++c)
                Ks[(ty * 4 + r) * 68 + tx * 4 + c] = s4[r][c];   // P -> Ks buffer
        __syncthreads();

        // O = alpha * O + P V
        #pragma unroll
        for (int r = 0; r < 4; ++r)
            #pragma unroll
            for (int c = 0; c < 4; ++c) acc[r][c] *= alpha[r];
        #pragma unroll 8
        for (int j = 0; j < 64; ++j) {
            float4 v = *(const float4*)(Vs + j * 68 + tx * 4);
            float p0 = Ks[(ty * 4 + 0) * 68 + j];
            float p1 = Ks[(ty * 4 + 1) * 68 + j];
            float p2 = Ks[(ty * 4 + 2) * 68 + j];
            float p3 = Ks[(ty * 4 + 3) * 68 + j];
            acc[0][0] += p0 * v.x; acc[0][1] += p0 * v.y; acc[0][2] += p0 * v.z; acc[0][3] += p0 * v.w;
            acc[1][0] += p1 * v.x; acc[1][1] += p1 * v.y; acc[1][2] += p1 * v.z; acc[1][3] += p1 * v.w;
            acc[2][0] += p2 * v.x; acc[2][1] += p2 * v.y; acc[2][2] += p2 * v.z; acc[2][3] += p2 * v.w;
            acc[3][0] += p3 * v.x; acc[3][1] += p3 * v.y; acc[3][2] += p3 * v.z; acc[3][3] += p3 * v.w;
        }
    }

    // Normalize and write O in [B, L, H*DK] layout
    #pragma unroll
    for (int r = 0; r < 4; ++r) {
        float inv = 1.0f / lreg[r];
        float4 o4 = make_float4(acc[r][0] * inv, acc[r][1] * inv,
                                acc[r][2] * inv, acc[r][3] * inv);
        *(float4*)(out + (size_t)(b * L_ + qi * 64 + ty * 4 + r) * DM
                   + h * 64 + tx * 4) = o4;
    }
}

// ---------------- launch ----------------------------------------------------
extern "C" void kernel_launch(void* const* d_in, const int* in_sizes, int n_in,
                              void* d_out, int out_size) {
    const float* x   = (const float*)d_in[0];
    const float* Win = (const float*)d_in[1];
    const float* Wo  = (const float*)d_in[2];
    float* out = (float*)d_out;

    float *ph, *pqkv, *po, *pc, *ps;
    cudaGetSymbolAddress((void**)&ph,   g_h);
    cudaGetSymbolAddress((void**)&pqkv, g_qkv);
    cudaGetSymbolAddress((void**)&po,   g_o);
    cudaGetSymbolAddress((void**)&pc,   g_cos);
    cudaGetSymbolAddress((void**)&ps,   g_sin);

    cudaFuncSetAttribute(attn_kernel, cudaFuncAttributeMaxDynamicSharedMemorySize,
                         ATTN_SMEM);

    ln_kernel<<<MROWS, 256>>>(x, ph);
    rope_table_kernel<<<256, 256>>>(pc, ps);
    sgemm_nt<<<dim3(3 * DM / 128, MROWS / 128), 256>>>(ph, Win, pqkv, MROWS, 3 * DM, DM);
    rope_apply_kernel<<<(MROWS * 1024) / 256, 256>>>(pqkv, pc, ps);
    attn_kernel<<<dim3(L_ / 64, H_, B_), 256, ATTN_SMEM>>>(pqkv, po);
    sgemm_nt<<<dim3(DM / 128, MROWS / 128), 256>>>(po, Wo, out, MROWS, DM, DM);
}

// round 6
// speedup vs baseline: 1.6296x; 1.6296x over previous
#include <cuda_runtime.h>
#include <cuda_fp16.h>
#include <math.h>
#include <stdint.h>

#define B_  4
#define L_  2048
#define DM  1024
#define H_  16
#define DK  64
#define MROWS (B_ * L_)          // 8192

// ---------------- scratch (device globals; no allocation allowed) ----------
__device__ float g_h[(size_t)MROWS * DM];            // 32 MB  layernorm out
__device__ float g_qkv[(size_t)MROWS * 3 * DM];      // 96 MB  qkv (rope in place)
__device__ float g_o[(size_t)MROWS * DM];            // 32 MB  attention out
__device__ float g_cos[L_ * 32];
__device__ float g_sin[L_ * 32];

// ==================== mma.sync helpers (sm_80-era PTX, HMMA) ===============
__device__ __forceinline__ uint32_t smem_u32(const void* p) {
    uint32_t a;
    asm("{ .reg .u64 t; cvta.to.shared.u64 t, %1; cvt.u32.u64 %0, t; }"
        : "=r"(a) : "l"(p));
    return a;
}
__device__ __forceinline__ void ldsm4(uint32_t& r0, uint32_t& r1,
                                      uint32_t& r2, uint32_t& r3, uint32_t addr) {
    asm volatile("ldmatrix.sync.aligned.m8n8.x4.shared.b16 {%0,%1,%2,%3}, [%4];"
                 : "=r"(r0), "=r"(r1), "=r"(r2), "=r"(r3) : "r"(addr));
}
__device__ __forceinline__ void mma16816(float* c, const uint32_t* a, const uint32_t* b) {
    asm volatile(
        "mma.sync.aligned.m16n8k16.row.col.f32.f16.f16.f32 "
        "{%0,%1,%2,%3}, {%4,%5,%6,%7}, {%8,%9}, {%0,%1,%2,%3};"
        : "+f"(c[0]), "+f"(c[1]), "+f"(c[2]), "+f"(c[3])
        : "r"(a[0]), "r"(a[1]), "r"(a[2]), "r"(a[3]), "r"(b[0]), "r"(b[1]));
}
__device__ __forceinline__ uint32_t f2h2(float lo, float hi) {
    __half2 h = __floats2half2_rn(lo, hi);
    return *(uint32_t*)&h;
}

// ================= fp16 HMMA NT GEMM: C[M,N] = A[M,K] * B[N,K]^T ===========
// CTA tile 128x128, K chunk 32, double-buffered smem.
// 8 warps: 2 (M) x 4 (N), warp tile 64x32. m16n8k16 microtiles.
// Smem rows: 40 halves (80 B) pitch -> ldmatrix 8-row wavefronts are
// conflict-free (20*r mod 32 is a perfect bank-group permutation).
#define GPITCH 40                       // halves per smem row
#define GSTAGE (128 * GPITCH)           // halves per tile per stage

__global__ __launch_bounds__(256)
void gemm_f16(const float* __restrict__ A, const float* __restrict__ Bm,
              float* __restrict__ C, int M, int N, int K) {
    __shared__ __half smA[2][GSTAGE];
    __shared__ __half smB[2][GSTAGE];

    const int tid = threadIdx.x;
    const int w = tid >> 5, lane = tid & 31;
    const int wm = w & 1, wn = w >> 1;          // warp grid 2 x 4
    const int bx = blockIdx.x, by = blockIdx.y;

    const float* Ab = A + (size_t)by * 128 * K;
    const float* Bb = Bm + (size_t)bx * 128 * K;

    // staging map: idx = tid + i*256 -> row = idx>>3, c4 = idx&7 (4-float group)
    const int sr = tid >> 3;
    const int sc = (tid & 7) * 4;

    float acc[4][4][4];
    #pragma unroll
    for (int i = 0; i < 4; ++i)
        #pragma unroll
        for (int j = 0; j < 4; ++j)
            #pragma unroll
            for (int e = 0; e < 4; ++e) acc[i][j][e] = 0.f;

    const uint32_t aBase0 = smem_u32(&smA[0][0]);
    const uint32_t bBase0 = smem_u32(&smB[0][0]);
    const uint32_t stageBytes = GSTAGE * 2;

    // ---- prologue: stage chunk 0 into buffer 0 ----
    #pragma unroll
    for (int i = 0; i < 4; ++i) {
        int r = sr + i * 32;
        float4 va = *(const float4*)(Ab + (size_t)r * K + sc);
        float4 vb = *(const float4*)(Bb + (size_t)r * K + sc);
        *(uint2*)&smA[0][r * GPITCH + sc] = make_uint2(f2h2(va.x, va.y), f2h2(va.z, va.w));
        *(uint2*)&smB[0][r * GPITCH + sc] = make_uint2(f2h2(vb.x, vb.y), f2h2(vb.z, vb.w));
    }
    __syncthreads();

    // ldmatrix lane addressing (byte offsets within a stage)
    // A: row = wm*64 + mi*16 + (lane&15), colhalf = (lane>>4)*8
    const uint32_t aLaneOff = (uint32_t)(wm * 64 + (lane & 15)) * (GPITCH * 2)
                            + (uint32_t)(lane >> 4) * 16;
    // B: row = wn*32 + nb*16 + ((lane>>4)*8 + (lane&7)), colhalf = ((lane>>3)&1)*8
    const uint32_t bLaneOff = (uint32_t)(wn * 32 + ((lane >> 4) * 8) + (lane & 7)) * (GPITCH * 2)
                            + (uint32_t)((lane >> 3) & 1) * 16;

    const int ntiles = K >> 5;
    for (int t = 0; t < ntiles; ++t) {
        const int cur = t & 1;

        // load next chunk to registers (as halves)
        uint2 nA[4], nB[4];
        if (t + 1 < ntiles) {
            int k0 = (t + 1) << 5;
            #pragma unroll
            for (int i = 0; i < 4; ++i) {
                int r = sr + i * 32;
                float4 va = *(const float4*)(Ab + (size_t)r * K + k0 + sc);
                float4 vb = *(const float4*)(Bb + (size_t)r * K + k0 + sc);
                nA[i] = make_uint2(f2h2(va.x, va.y), f2h2(va.z, va.w));
                nB[i] = make_uint2(f2h2(vb.x, vb.y), f2h2(vb.z, vb.w));
            }
        }

        // compute on current buffer: two k16 steps
        const uint32_t aS = aBase0 + cur * stageBytes;
        const uint32_t bS = bBase0 + cur * stageBytes;
        #pragma unroll
        for (int ks = 0; ks < 2; ++ks) {
            uint32_t af[4][4], bf[4][2];
            #pragma unroll
            for (int mi = 0; mi < 4; ++mi)
                ldsm4(af[mi][0], af[mi][1], af[mi][2], af[mi][3],
                      aS + aLaneOff + (uint32_t)mi * 16 * (GPITCH * 2) + ks * 32);
            #pragma unroll
            for (int nb = 0; nb < 2; ++nb) {
                uint32_t r0, r1, r2, r3;
                ldsm4(r0, r1, r2, r3,
                      bS + bLaneOff + (uint32_t)nb * 16 * (GPITCH * 2) + ks * 32);
                bf[nb * 2][0] = r0; bf[nb * 2][1] = r1;
                bf[nb * 2 + 1][0] = r2; bf[nb * 2 + 1][1] = r3;
            }
            #pragma unroll
            for (int mi = 0; mi < 4; ++mi)
                #pragma unroll
                for (int ni = 0; ni < 4; ++ni)
                    mma16816(acc[mi][ni], af[mi], bf[ni]);
        }

        // store next chunk into other buffer
        if (t + 1 < ntiles) {
            int nxt = cur ^ 1;
            #pragma unroll
            for (int i = 0; i < 4; ++i) {
                int r = sr + i * 32;
                *(uint2*)&smA[nxt][r * GPITCH + sc] = nA[i];
                *(uint2*)&smB[nxt][r * GPITCH + sc] = nB[i];
            }
        }
        __syncthreads();
    }

    // ---- epilogue: acc -> C ----
    const int rbase = by * 128 + wm * 64 + (lane >> 2);
    const int cbase = bx * 128 + wn * 32 + (lane & 3) * 2;
    #pragma unroll
    for (int mi = 0; mi < 4; ++mi) {
        #pragma unroll
        for (int ni = 0; ni < 4; ++ni) {
            float* p0 = C + (size_t)(rbase + mi * 16) * N + cbase + ni * 8;
            float* p1 = p0 + (size_t)8 * N;
            *(float2*)p0 = make_float2(acc[mi][ni][0], acc[mi][ni][1]);
            *(float2*)p1 = make_float2(acc[mi][ni][2], acc[mi][ni][3]);
        }
    }
}

// ---------------- LayerNorm: one block per row (1024 elems, 256 thr) -------
__global__ void ln_kernel(const float* __restrict__ x, float* __restrict__ h) {
    __shared__ float red[8];
    int row = blockIdx.x;
    const float4* xr = (const float4*)(x + (size_t)row * DM);
    float4 v = xr[threadIdx.x];

    float s = v.x + v.y + v.z + v.w;
    #pragma unroll
    for (int o = 16; o; o >>= 1) s += __shfl_xor_sync(0xffffffffu, s, o);
    if ((threadIdx.x & 31) == 0) red[threadIdx.x >> 5] = s;
    __syncthreads();
    float tot = red[0] + red[1] + red[2] + red[3] + red[4] + red[5] + red[6] + red[7];
    float mean = tot * (1.0f / 1024.0f);

    float dx = v.x - mean, dy = v.y - mean, dz = v.z - mean, dw = v.w - mean;
    float sq = dx * dx + dy * dy + dz * dz + dw * dw;
    __syncthreads();
    #pragma unroll
    for (int o = 16; o; o >>= 1) sq += __shfl_xor_sync(0xffffffffu, sq, o);
    if ((threadIdx.x & 31) == 0) red[threadIdx.x >> 5] = sq;
    __syncthreads();
    float var = (red[0] + red[1] + red[2] + red[3] + red[4] + red[5] + red[6] + red[7])
                * (1.0f / 1024.0f);
    float inv = rsqrtf(var + 1e-8f);

    float4 o4 = make_float4(dx * inv, dy * inv, dz * inv, dw * inv);
    ((float4*)(h + (size_t)row * DM))[threadIdx.x] = o4;
}

// ---------------- RoPE table (double precision, tiny) ----------------------
__global__ void rope_table_kernel(float* __restrict__ ct, float* __restrict__ st) {
    int idx = blockIdx.x * blockDim.x + threadIdx.x;   // 65536 total
    int l = idx >> 5;
    int i = idx & 31;
    double inv = exp(-(double)i * (log(10000.0) / 32.0));
    double a = (double)l * inv;
    ct[idx] = (float)cos(a);
    st[idx] = (float)sin(a);
}

// ---------------- RoPE apply, in place on q and k sections of qkv ----------
__global__ void rope_apply_kernel(float* __restrict__ qkv,
                                  const float* __restrict__ ct,
                                  const float* __restrict__ st) {
    int idx = blockIdx.x * blockDim.x + threadIdx.x;   // 8,388,608 total
    int pair = idx & 31;
    int head = (idx >> 5) & 15;
    int sec  = (idx >> 9) & 1;          // 0 = q, 1 = k
    int row  = idx >> 10;               // 0..8191
    int l    = row & (L_ - 1);
    size_t off = (size_t)row * 3072 + sec * 1024 + head * 64 + pair * 2;
    float2 v = *(float2*)(qkv + off);
    int ti = l * 32 + pair;
    float c = ct[ti], s = st[ti];
    float2 r = make_float2(v.x * c - v.y * s, v.x * s + v.y * c);
    *(float2*)(qkv + off) = r;
}

// ---------------- Flash attention (causal), fp32 ---------------------------
#define ATTN_SMEM ((64 * 64 + 2 * 64 * 68) * 4)
#define NEG_BIG (-1e30f)

__global__ __launch_bounds__(256)
void attn_kernel(const float* __restrict__ qkv, float* __restrict__ out) {
    extern __shared__ float sm[];
    float* Qs = sm;                 // 64 x 64
    float* Ks = Qs + 64 * 64;       // 64 x 68, reused as P after softmax
    float* Vs = Ks + 64 * 68;       // 64 x 68

    int qi = blockIdx.x, h = blockIdx.y, b = blockIdx.z;
    int tid = threadIdx.x;
    int tx = tid & 15, ty = tid >> 4;
    const float scale = 0.125f;     // 1/sqrt(64)

    for (int i = tid; i < 64 * 16; i += 256) {
        int r = i >> 4, c = (i & 15) << 2;
        const float* p = qkv + (size_t)(b * L_ + qi * 64 + r) * 3072 + h * 64 + c;
        float4 v = *(const float4*)p;
        v.x *= scale; v.y *= scale; v.z *= scale; v.w *= scale;
        *(float4*)(Qs + r * 64 + c) = v;
    }

    float acc[4][4];
    #pragma unroll
    for (int r = 0; r < 4; ++r)
        #pragma unroll
        for (int c = 0; c < 4; ++c) acc[r][c] = 0.f;
    float mreg[4], lreg[4];
    #pragma unroll
    for (int r = 0; r < 4; ++r) { mreg[r] = NEG_BIG; lreg[r] = 0.f; }

    for (int kt = 0; kt <= qi; ++kt) {
        __syncthreads();
        for (int i = tid; i < 64 * 16; i += 256) {
            int r = i >> 4, c = (i & 15) << 2;
            const float* p = qkv + (size_t)(b * L_ + kt * 64 + r) * 3072 + 1024 + h * 64 + c;
            *(float4*)(Ks + r * 68 + c) = *(const float4*)p;
            *(float4*)(Vs + r * 68 + c) = *(const float4*)(p + 1024);
        }
        __syncthreads();

        float s4[4][4];
        #pragma unroll
        for (int r = 0; r < 4; ++r)
            #pragma unroll
            for (int c = 0; c < 4; ++c) s4[r][c] = 0.f;
        #pragma unroll 4
        for (int d4 = 0; d4 < 16; ++d4) {
            float4 a[4], bb[4];
            #pragma unroll
            for (int r = 0; r < 4; ++r)
                a[r] = *(const float4*)(Qs + (ty * 4 + r) * 64 + d4 * 4);
            #pragma unroll
            for (int c = 0; c < 4; ++c)
                bb[c] = *(const float4*)(Ks + (tx * 4 + c) * 68 + d4 * 4);
            #pragma unroll
            for (int r = 0; r < 4; ++r)
                #pragma unroll
                for (int c = 0; c < 4; ++c)
                    s4[r][c] += a[r].x * bb[c].x + a[r].y * bb[c].y
                              + a[r].z * bb[c].z + a[r].w * bb[c].w;
        }
        if (kt == qi) {
            #pragma unroll
            for (int r = 0; r < 4; ++r)
                #pragma unroll
                for (int c = 0; c < 4; ++c)
                    if (tx * 4 + c > ty * 4 + r) s4[r][c] = NEG_BIG;
        }

        float alpha[4];
        #pragma unroll
        for (int r = 0; r < 4; ++r) {
            float mx = fmaxf(fmaxf(s4[r][0], s4[r][1]), fmaxf(s4[r][2], s4[r][3]));
            #pragma unroll
            for (int o = 8; o; o >>= 1) mx = fmaxf(mx, __shfl_xor_sync(0xffffffffu, mx, o));
            mx = fmaxf(mx, mreg[r]);
            float sum = 0.f;
            #pragma unroll
            for (int c = 0; c < 4; ++c) {
                float p = __expf(s4[r][c] - mx);
                s4[r][c] = p;
                sum += p;
            }
            #pragma unroll
            for (int o = 8; o; o >>= 1) sum += __shfl_xor_sync(0xffffffffu, sum, o);
            alpha[r] = __expf(mreg[r] - mx);
            lreg[r] = lreg[r] * alpha[r] + sum;
            mreg[r] = mx;
        }

        __syncthreads();
        #pragma unroll
        for (int r = 0; r < 4; ++r)
            #pragma unroll
            for (int c = 0; c < 4; ++c)
                Ks[(ty * 4 + r) * 68 + tx * 4 + c] = s4[r][c];
        __syncthreads();

        #pragma unroll
        for (int r = 0; r < 4; ++r)
            #pragma unroll
            for (int c = 0; c < 4; ++c) acc[r][c] *= alpha[r];
        #pragma unroll 8
        for (int j = 0; j < 64; ++j) {
            float4 v = *(const float4*)(Vs + j * 68 + tx * 4);
            float p0 = Ks[(ty * 4 + 0) * 68 + j];
            float p1 = Ks[(ty * 4 + 1) * 68 + j];
            float p2 = Ks[(ty * 4 + 2) * 68 + j];
            float p3 = Ks[(ty * 4 + 3) * 68 + j];
            acc[0][0] += p0 * v.x; acc[0][1] += p0 * v.y; acc[0][2] += p0 * v.z; acc[0][3] += p0 * v.w;
            acc[1][0] += p1 * v.x; acc[1][1] += p1 * v.y; acc[1][2] += p1 * v.z; acc[1][3] += p1 * v.w;
            acc[2][0] += p2 * v.x; acc[2][1] += p2 * v.y; acc[2][2] += p2 * v.z; acc[2][3] += p2 * v.w;
            acc[3][0] += p3 * v.x; acc[3][1] += p3 * v.y; acc[3][2] += p3 * v.z; acc[3][3] += p3 * v.w;
        }
    }

    #pragma unroll
    for (int r = 0; r < 4; ++r) {
        float inv = 1.0f / lreg[r];
        float4 o4 = make_float4(acc[r][0] * inv, acc[r][1] * inv,
                                acc[r][2] * inv, acc[r][3] * inv);
        *(float4*)(out + (size_t)(b * L_ + qi * 64 + ty * 4 + r) * DM
                   + h * 64 + tx * 4) = o4;
    }
}

// ---------------- launch ----------------------------------------------------
extern "C" void kernel_launch(void* const* d_in, const int* in_sizes, int n_in,
                              void* d_out, int out_size) {
    const float* x   = (const float*)d_in[0];
    const float* Win = (const float*)d_in[1];
    const float* Wo  = (const float*)d_in[2];
    float* out = (float*)d_out;

    float *ph, *pqkv, *po, *pc, *ps;
    cudaGetSymbolAddress((void**)&ph,   g_h);
    cudaGetSymbolAddress((void**)&pqkv, g_qkv);
    cudaGetSymbolAddress((void**)&po,   g_o);
    cudaGetSymbolAddress((void**)&pc,   g_cos);
    cudaGetSymbolAddress((void**)&ps,   g_sin);

    cudaFuncSetAttribute(attn_kernel, cudaFuncAttributeMaxDynamicSharedMemorySize,
                         ATTN_SMEM);

    ln_kernel<<<MROWS, 256>>>(x, ph);
    rope_table_kernel<<<256, 256>>>(pc, ps);
    gemm_f16<<<dim3(3 * DM / 128, MROWS / 128), 256>>>(ph, Win, pqkv, MROWS, 3 * DM, DM);
    rope_apply_kernel<<<(MROWS * 1024) / 256, 256>>>(pqkv, pc, ps);
    attn_kernel<<<dim3(L_ / 64, H_, B_), 256, ATTN_SMEM>>>(pqkv, po);
    gemm_f16<<<dim3(DM / 128, MROWS / 128), 256>>>(po, Wo, out, MROWS, DM, DM);
}

// round 7
// speedup vs baseline: 6.3551x; 3.8998x over previous
#include <cuda_runtime.h>
#include <cuda_fp16.h>
#include <math.h>
#include <stdint.h>

#define B_  4
#define L_  2048
#define DM  1024
#define H_  16
#define DK  64
#define MROWS (B_ * L_)          // 8192

// ---------------- scratch (device globals; no allocation allowed) ----------
__device__ float  g_h[(size_t)MROWS * DM];            // 32 MB  layernorm out
__device__ float  g_qkv[(size_t)MROWS * 3 * DM];      // 96 MB  qkv fp32 (pre-rope)
__device__ __half g_qkvh[(size_t)MROWS * 3 * DM];     // 48 MB  roped fp16 q,k + fp16 v
__device__ float  g_o[(size_t)MROWS * DM];            // 32 MB  attention out
__device__ float  g_cos[L_ * 32];
__device__ float  g_sin[L_ * 32];

// ==================== mma.sync helpers (sm_80-era PTX, HMMA) ===============
__device__ __forceinline__ uint32_t smem_u32(const void* p) {
    uint32_t a;
    asm("{ .reg .u64 t; cvta.to.shared.u64 t, %1; cvt.u32.u64 %0, t; }"
        : "=r"(a) : "l"(p));
    return a;
}
__device__ __forceinline__ void ldsm4(uint32_t& r0, uint32_t& r1,
                                      uint32_t& r2, uint32_t& r3, uint32_t addr) {
    asm volatile("ldmatrix.sync.aligned.m8n8.x4.shared.b16 {%0,%1,%2,%3}, [%4];"
                 : "=r"(r0), "=r"(r1), "=r"(r2), "=r"(r3) : "r"(addr));
}
__device__ __forceinline__ void ldsm4t(uint32_t& r0, uint32_t& r1,
                                       uint32_t& r2, uint32_t& r3, uint32_t addr) {
    asm volatile("ldmatrix.sync.aligned.m8n8.x4.trans.shared.b16 {%0,%1,%2,%3}, [%4];"
                 : "=r"(r0), "=r"(r1), "=r"(r2), "=r"(r3) : "r"(addr));
}
__device__ __forceinline__ void mma16816(float* c, const uint32_t* a, const uint32_t* b) {
    asm volatile(
        "mma.sync.aligned.m16n8k16.row.col.f32.f16.f16.f32 "
        "{%0,%1,%2,%3}, {%4,%5,%6,%7}, {%8,%9}, {%0,%1,%2,%3};"
        : "+f"(c[0]), "+f"(c[1]), "+f"(c[2]), "+f"(c[3])
        : "r"(a[0]), "r"(a[1]), "r"(a[2]), "r"(a[3]), "r"(b[0]), "r"(b[1]));
}
__device__ __forceinline__ uint32_t f2h2(float lo, float hi) {
    __half2 h = __floats2half2_rn(lo, hi);
    return *(uint32_t*)&h;
}
__device__ __forceinline__ void cp16(uint32_t dst, const void* src) {
    asm volatile("cp.async.cg.shared.global [%0], [%1], 16;"
                 :: "r"(dst), "l"(src) : "memory");
}
#define CP_COMMIT() asm volatile("cp.async.commit_group;" ::: "memory")
#define CP_WAIT(n)  asm volatile("cp.async.wait_group %0;" :: "n"(n) : "memory")

// ================= fp16 HMMA NT GEMM: C[M,N] = A[M,K] * B[N,K]^T ===========
#define GPITCH 40                       // halves per smem row
#define GSTAGE (128 * GPITCH)           // halves per tile per stage

__global__ __launch_bounds__(256)
void gemm_f16(const float* __restrict__ A, const float* __restrict__ Bm,
              float* __restrict__ C, int M, int N, int K) {
    __shared__ __half smA[2][GSTAGE];
    __shared__ __half smB[2][GSTAGE];

    const int tid = threadIdx.x;
    const int w = tid >> 5, lane = tid & 31;
    const int wm = w & 1, wn = w >> 1;          // warp grid 2 x 4
    const int bx = blockIdx.x, by = blockIdx.y;

    const float* Ab = A + (size_t)by * 128 * K;
    const float* Bb = Bm + (size_t)bx * 128 * K;

    const int sr = tid >> 3;
    const int sc = (tid & 7) * 4;

    float acc[4][4][4];
    #pragma unroll
    for (int i = 0; i < 4; ++i)
        #pragma unroll
        for (int j = 0; j < 4; ++j)
            #pragma unroll
            for (int e = 0; e < 4; ++e) acc[i][j][e] = 0.f;

    const uint32_t aBase0 = smem_u32(&smA[0][0]);
    const uint32_t bBase0 = smem_u32(&smB[0][0]);
    const uint32_t stageBytes = GSTAGE * 2;

    #pragma unroll
    for (int i = 0; i < 4; ++i) {
        int r = sr + i * 32;
        float4 va = *(const float4*)(Ab + (size_t)r * K + sc);
        float4 vb = *(const float4*)(Bb + (size_t)r * K + sc);
        *(uint2*)&smA[0][r * GPITCH + sc] = make_uint2(f2h2(va.x, va.y), f2h2(va.z, va.w));
        *(uint2*)&smB[0][r * GPITCH + sc] = make_uint2(f2h2(vb.x, vb.y), f2h2(vb.z, vb.w));
    }
    __syncthreads();

    const uint32_t aLaneOff = (uint32_t)(wm * 64 + (lane & 15)) * (GPITCH * 2)
                            + (uint32_t)(lane >> 4) * 16;
    const uint32_t bLaneOff = (uint32_t)(wn * 32 + ((lane >> 4) * 8) + (lane & 7)) * (GPITCH * 2)
                            + (uint32_t)((lane >> 3) & 1) * 16;

    const int ntiles = K >> 5;
    for (int t = 0; t < ntiles; ++t) {
        const int cur = t & 1;

        uint2 nA[4], nB[4];
        if (t + 1 < ntiles) {
            int k0 = (t + 1) << 5;
            #pragma unroll
            for (int i = 0; i < 4; ++i) {
                int r = sr + i * 32;
                float4 va = *(const float4*)(Ab + (size_t)r * K + k0 + sc);
                float4 vb = *(const float4*)(Bb + (size_t)r * K + k0 + sc);
                nA[i] = make_uint2(f2h2(va.x, va.y), f2h2(va.z, va.w));
                nB[i] = make_uint2(f2h2(vb.x, vb.y), f2h2(vb.z, vb.w));
            }
        }

        const uint32_t aS = aBase0 + cur * stageBytes;
        const uint32_t bS = bBase0 + cur * stageBytes;
        #pragma unroll
        for (int ks = 0; ks < 2; ++ks) {
            uint32_t af[4][4], bf[4][2];
            #pragma unroll
            for (int mi = 0; mi < 4; ++mi)
                ldsm4(af[mi][0], af[mi][1], af[mi][2], af[mi][3],
                      aS + aLaneOff + (uint32_t)mi * 16 * (GPITCH * 2) + ks * 32);
            #pragma unroll
            for (int nb = 0; nb < 2; ++nb) {
                uint32_t r0, r1, r2, r3;
                ldsm4(r0, r1, r2, r3,
                      bS + bLaneOff + (uint32_t)nb * 16 * (GPITCH * 2) + ks * 32);
                bf[nb * 2][0] = r0; bf[nb * 2][1] = r1;
                bf[nb * 2 + 1][0] = r2; bf[nb * 2 + 1][1] = r3;
            }
            #pragma unroll
            for (int mi = 0; mi < 4; ++mi)
                #pragma unroll
                for (int ni = 0; ni < 4; ++ni)
                    mma16816(acc[mi][ni], af[mi], bf[ni]);
        }

        if (t + 1 < ntiles) {
            int nxt = cur ^ 1;
            #pragma unroll
            for (int i = 0; i < 4; ++i) {
                int r = sr + i * 32;
                *(uint2*)&smA[nxt][r * GPITCH + sc] = nA[i];
                *(uint2*)&smB[nxt][r * GPITCH + sc] = nB[i];
            }
        }
        __syncthreads();
    }

    const int rbase = by * 128 + wm * 64 + (lane >> 2);
    const int cbase = bx * 128 + wn * 32 + (lane & 3) * 2;
    #pragma unroll
    for (int mi = 0; mi < 4; ++mi) {
        #pragma unroll
        for (int ni = 0; ni < 4; ++ni) {
            float* p0 = C + (size_t)(rbase + mi * 16) * N + cbase + ni * 8;
            float* p1 = p0 + (size_t)8 * N;
            *(float2*)p0 = make_float2(acc[mi][ni][0], acc[mi][ni][1]);
            *(float2*)p1 = make_float2(acc[mi][ni][2], acc[mi][ni][3]);
        }
    }
}

// ---------------- LayerNorm ------------------------------------------------
__global__ void ln_kernel(const float* __restrict__ x, float* __restrict__ h) {
    __shared__ float red[8];
    int row = blockIdx.x;
    const float4* xr = (const float4*)(x + (size_t)row * DM);
    float4 v = xr[threadIdx.x];

    float s = v.x + v.y + v.z + v.w;
    #pragma unroll
    for (int o = 16; o; o >>= 1) s += __shfl_xor_sync(0xffffffffu, s, o);
    if ((threadIdx.x & 31) == 0) red[threadIdx.x >> 5] = s;
    __syncthreads();
    float tot = red[0] + red[1] + red[2] + red[3] + red[4] + red[5] + red[6] + red[7];
    float mean = tot * (1.0f / 1024.0f);

    float dx = v.x - mean, dy = v.y - mean, dz = v.z - mean, dw = v.w - mean;
    float sq = dx * dx + dy * dy + dz * dz + dw * dw;
    __syncthreads();
    #pragma unroll
    for (int o = 16; o; o >>= 1) sq += __shfl_xor_sync(0xffffffffu, sq, o);
    if ((threadIdx.x & 31) == 0) red[threadIdx.x >> 5] = sq;
    __syncthreads();
    float var = (red[0] + red[1] + red[2] + red[3] + red[4] + red[5] + red[6] + red[7])
                * (1.0f / 1024.0f);
    float inv = rsqrtf(var + 1e-8f);

    float4 o4 = make_float4(dx * inv, dy * inv, dz * inv, dw * inv);
    ((float4*)(h + (size_t)row * DM))[threadIdx.x] = o4;
}

// ---------------- RoPE table -----------------------------------------------
__global__ void rope_table_kernel(float* __restrict__ ct, float* __restrict__ st) {
    int idx = blockIdx.x * blockDim.x + threadIdx.x;   // 65536 total
    int l = idx >> 5;
    int i = idx & 31;
    double inv = exp(-(double)i * (log(10000.0) / 32.0));
    double a = (double)l * inv;
    ct[idx] = (float)cos(a);
    st[idx] = (float)sin(a);
}

// -------- RoPE + fp16 convert: fp32 qkv -> fp16 qkvh (q pre-scaled) --------
__global__ void rope_cvt_kernel(const float* __restrict__ qkv,
                                __half* __restrict__ qkvh,
                                const float* __restrict__ ct,
                                const float* __restrict__ st) {
    int idx = blockIdx.x * blockDim.x + threadIdx.x;   // MROWS*1536 pairs
    int row = idx / 1536;
    int rem = idx - row * 1536;
    size_t off = (size_t)row * 3072 + rem * 2;
    float2 v = *(const float2*)(qkv + off);
    float2 r;
    if (rem < 1024) {                     // q or k: rotate
        int pair = rem & 31;
        int l = row & (L_ - 1);
        float c = ct[l * 32 + pair], s = st[l * 32 + pair];
        r.x = v.x * c - v.y * s;
        r.y = v.x * s + v.y * c;
        if (rem < 512) { r.x *= 0.125f; r.y *= 0.125f; }   // pre-scale q
    } else {
        r = v;                            // v: convert only
    }
    __half2 hv = __floats2half2_rn(r.x, r.y);
    *(__half2*)(qkvh + off) = hv;
}

// ---------------- Flash attention (causal), fp16 HMMA ----------------------
// grid (L/128, H, B), 256 threads (8 warps x 16 q-rows). BK=64.
// Smem: Q 128x72h, K/V double-buffered 64x72h each. Pitch 72 halves = 144 B
// -> ldmatrix 8-row wavefronts conflict-free.
#define APITCH 72
#define ASM_Q   0
#define ASM_K0  (128 * APITCH)
#define ASM_V0  (ASM_K0 + 64 * APITCH)
#define ASM_K1  (ASM_V0 + 64 * APITCH)
#define ASM_V1  (ASM_K1 + 64 * APITCH)
#define ATTN_SMEM ((ASM_V1 + 64 * APITCH) * 2)    // bytes (55296)
#define NEG_BIG (-1e30f)

__global__ __launch_bounds__(256)
void attn_mma(const __half* __restrict__ qkvh, float* __restrict__ out) {
    extern __shared__ __half sh[];
    __half* Qs = sh;

    const int qi = (int)gridDim.x - 1 - (int)blockIdx.x;  // heavy CTAs first
    const int h = blockIdx.y, b = blockIdx.z;
    const int tid = threadIdx.x, w = tid >> 5, lane = tid & 31;
    const int g = lane >> 2, t = lane & 3;
    const size_t rowblk = (size_t)(b * L_ + qi * 128);

    // ---- prologue: Q tile + first K/V tile via cp.async ----
    #pragma unroll
    for (int j = 0; j < 4; ++j) {
        int c = tid + j * 256;                 // 0..1023
        int r = c >> 3, ch = c & 7;
        cp16(smem_u32(Qs + r * APITCH + ch * 8),
             qkvh + (rowblk + r) * 3072 + h * 64 + ch * 8);
    }
    {
        const __half* kb = qkvh + (size_t)(b * L_) * 3072 + 1024 + h * 64;
        #pragma unroll
        for (int j = 0; j < 4; ++j) {
            int c = tid + j * 256;
            int r = (c >> 3) & 63, ch = c & 7, isv = c >> 9;
            cp16(smem_u32(sh + (isv ? ASM_V0 : ASM_K0) + r * APITCH + ch * 8),
                 kb + (size_t)r * 3072 + isv * 1024 + ch * 8);
        }
    }
    CP_COMMIT();

    float o[8][4];
    #pragma unroll
    for (int n = 0; n < 8; ++n)
        #pragma unroll
        for (int e = 0; e < 4; ++e) o[n][e] = 0.f;
    float m0 = NEG_BIG, m1 = NEG_BIG, l0 = 0.f, l1 = 0.f;
    uint32_t aq[4][4];

    const int ktmax = 2 * qi + 1;
    const int qrow0 = qi * 128 + w * 16 + g;   // global q row for c0/c1
    const int qrmin = qi * 128 + w * 16;

    for (int kt = 0; kt <= ktmax; ++kt) {
        const int buf = kt & 1;
        const int koff = buf ? ASM_K1 : ASM_K0;
        const int voff = buf ? ASM_V1 : ASM_V0;

        if (kt < ktmax) {
            const int nb = buf ^ 1;
            const __half* kb = qkvh + (size_t)(b * L_ + (kt + 1) * 64) * 3072 + 1024 + h * 64;
            #pragma unroll
            for (int j = 0; j < 4; ++j) {
                int c = tid + j * 256;
                int r = (c >> 3) & 63, ch = c & 7, isv = c >> 9;
                cp16(smem_u32(sh + (isv ? (nb ? ASM_V1 : ASM_V0) : (nb ? ASM_K1 : ASM_K0))
                              + r * APITCH + ch * 8),
                     kb + (size_t)r * 3072 + isv * 1024 + ch * 8);
            }
            CP_COMMIT();
            CP_WAIT(1);
        } else {
            CP_WAIT(0);
        }
        __syncthreads();

        if (kt == 0) {        // Q fragments, once
            uint32_t qaddr = smem_u32(Qs + (w * 16 + (lane & 15)) * APITCH + (lane >> 4) * 8);
            #pragma unroll
            for (int ks = 0; ks < 4; ++ks)
                ldsm4(aq[ks][0], aq[ks][1], aq[ks][2], aq[ks][3], qaddr + ks * 32);
        }

        // ---- S = Q K^T ----
        float sfr[8][4];
        #pragma unroll
        for (int n = 0; n < 8; ++n)
            #pragma unroll
            for (int e = 0; e < 4; ++e) sfr[n][e] = 0.f;
        #pragma unroll
        for (int ks = 0; ks < 4; ++ks) {
            #pragma unroll
            for (int np = 0; np < 4; ++np) {
                uint32_t r0, r1, r2, r3;
                ldsm4(r0, r1, r2, r3,
                      smem_u32(sh + koff
                               + (np * 16 + (lane >> 4) * 8 + (lane & 7)) * APITCH
                               + ((lane >> 3) & 1) * 8 + ks * 16));
                uint32_t b0[2] = {r0, r1}, b1[2] = {r2, r3};
                mma16816(sfr[np * 2], aq[ks], b0);
                mma16816(sfr[np * 2 + 1], aq[ks], b1);
            }
        }

        // ---- causal mask (only tiles overlapping the diagonal) ----
        if (kt * 64 + 63 > qrmin) {
            #pragma unroll
            for (int n = 0; n < 8; ++n) {
                int colb = kt * 64 + n * 8 + t * 2;
                #pragma unroll
                for (int e = 0; e < 4; ++e) {
                    int col = colb + (e & 1);
                    int row = qrow0 + (e >> 1) * 8;
                    if (col > row) sfr[n][e] = NEG_BIG;
                }
            }
        }

        // ---- online softmax (rows g and g+8; quad-lane reductions) ----
        float mx0 = NEG_BIG, mx1 = NEG_BIG;
        #pragma unroll
        for (int n = 0; n < 8; ++n) {
            mx0 = fmaxf(mx0, fmaxf(sfr[n][0], sfr[n][1]));
            mx1 = fmaxf(mx1, fmaxf(sfr[n][2], sfr[n][3]));
        }
        mx0 = fmaxf(mx0, __shfl_xor_sync(0xffffffffu, mx0, 1));
        mx0 = fmaxf(mx0, __shfl_xor_sync(0xffffffffu, mx0, 2));
        mx1 = fmaxf(mx1, __shfl_xor_sync(0xffffffffu, mx1, 1));
        mx1 = fmaxf(mx1, __shfl_xor_sync(0xffffffffu, mx1, 2));
        float nm0 = fmaxf(m0, mx0), nm1 = fmaxf(m1, mx1);
        float sum0 = 0.f, sum1 = 0.f;
        #pragma unroll
        for (int n = 0; n < 8; ++n) {
            sfr[n][0] = __expf(sfr[n][0] - nm0);
            sfr[n][1] = __expf(sfr[n][1] - nm0);
            sfr[n][2] = __expf(sfr[n][2] - nm1);
            sfr[n][3] = __expf(sfr[n][3] - nm1);
            sum0 += sfr[n][0] + sfr[n][1];
            sum1 += sfr[n][2] + sfr[n][3];
        }
        sum0 += __shfl_xor_sync(0xffffffffu, sum0, 1);
        sum0 += __shfl_xor_sync(0xffffffffu, sum0, 2);
        sum1 += __shfl_xor_sync(0xffffffffu, sum1, 1);
        sum1 += __shfl_xor_sync(0xffffffffu, sum1, 2);
        float a0 = __expf(m0 - nm0), a1 = __expf(m1 - nm1);
        l0 = l0 * a0 + sum0;
        l1 = l1 * a1 + sum1;
        m0 = nm0; m1 = nm1;
        #pragma unroll
        for (int n = 0; n < 8; ++n) {
            o[n][0] *= a0; o[n][1] *= a0;
            o[n][2] *= a1; o[n][3] *= a1;
        }

        // ---- O += P V ----
        #pragma unroll
        for (int ks = 0; ks < 4; ++ks) {
            uint32_t pa[4] = {
                f2h2(sfr[2 * ks][0],     sfr[2 * ks][1]),
                f2h2(sfr[2 * ks][2],     sfr[2 * ks][3]),
                f2h2(sfr[2 * ks + 1][0], sfr[2 * ks + 1][1]),
                f2h2(sfr[2 * ks + 1][2], sfr[2 * ks + 1][3])
            };
            #pragma unroll
            for (int np = 0; np < 4; ++np) {
                uint32_t r0, r1, r2, r3;
                ldsm4t(r0, r1, r2, r3,
                       smem_u32(sh + voff
                                + (ks * 16 + ((lane >> 3) & 1) * 8 + (lane & 7)) * APITCH
                                + np * 16 + (lane >> 4) * 8));
                uint32_t b0[2] = {r0, r1}, b1[2] = {r2, r3};
                mma16816(o[np * 2], pa, b0);
                mma16816(o[np * 2 + 1], pa, b1);
            }
        }
        __syncthreads();
    }

    // ---- normalize, write fp32 [B,L,DM] ----
    float inv0 = 1.0f / l0, inv1 = 1.0f / l1;
    float* op0 = out + (rowblk + w * 16 + g) * DM + h * 64 + t * 2;
    float* op1 = op0 + (size_t)8 * DM;
    #pragma unroll
    for (int n = 0; n < 8; ++n) {
        *(float2*)(op0 + n * 8) = make_float2(o[n][0] * inv0, o[n][1] * inv0);
        *(float2*)(op1 + n * 8) = make_float2(o[n][2] * inv1, o[n][3] * inv1);
    }
}

// ---------------- launch ----------------------------------------------------
extern "C" void kernel_launch(void* const* d_in, const int* in_sizes, int n_in,
                              void* d_out, int out_size) {
    const float* x   = (const float*)d_in[0];
    const float* Win = (const float*)d_in[1];
    const float* Wo  = (const float*)d_in[2];
    float* out = (float*)d_out;

    float *ph, *pqkv, *po, *pc, *ps;
    __half* pqh;
    cudaGetSymbolAddress((void**)&ph,   g_h);
    cudaGetSymbolAddress((void**)&pqkv, g_qkv);
    cudaGetSymbolAddress((void**)&pqh,  g_qkvh);
    cudaGetSymbolAddress((void**)&po,   g_o);
    cudaGetSymbolAddress((void**)&pc,   g_cos);
    cudaGetSymbolAddress((void**)&ps,   g_sin);

    cudaFuncSetAttribute(attn_mma, cudaFuncAttributeMaxDynamicSharedMemorySize,
                         ATTN_SMEM);

    ln_kernel<<<MROWS, 256>>>(x, ph);
    rope_table_kernel<<<256, 256>>>(pc, ps);
    gemm_f16<<<dim3(3 * DM / 128, MROWS / 128), 256>>>(ph, Win, pqkv, MROWS, 3 * DM, DM);
    rope_cvt_kernel<<<(MROWS * 1536) / 256, 256>>>(pqkv, pqh, pc, ps);
    attn_mma<<<dim3(L_ / 128, H_, B_), 256, ATTN_SMEM>>>(pqh, po);
    gemm_f16<<<dim3(DM / 128, MROWS / 128), 256>>>(po, Wo, out, MROWS, DM, DM);
}